// round 4
// baseline (speedup 1.0000x reference)
#include <cuda_runtime.h>
#include <cuda_fp16.h>

#define D        128
#define TILE_R   64
#define NTHREADS 256
#define PSTRIDE  132   // padded row stride (floats) for transposed Pi
#define USTRIDE  132   // padded row stride (floats) for u/v tiles

// Shared layout (floats):
//   sPiT [128*PSTRIDE]  : sPiT[k][j] = Pi[j][k]   (GEMM1: rotated = u @ Pi^T)
//   sPi  [128*128]      : sPi[k][c]  = Pi[k][c]   (GEMM2: recon = v @ Pi)
//   sU   [TILE_R*USTRIDE]
//   sV   [TILE_R*USTRIDE]
//   sNorm[TILE_R]
//   sCen [16]
#define SMEM_FLOATS (128*PSTRIDE + 128*128 + 2*TILE_R*USTRIDE + TILE_R + 16)

__global__ __launch_bounds__(NTHREADS, 1)
void tq_kernel(const float* __restrict__ x, const float* __restrict__ Pi,
               const float* __restrict__ cen, const float* __restrict__ bnd,
               float* __restrict__ out, int nrows, int ntiles)
{
    extern __shared__ float sm[];
    float* sPiT  = sm;
    float* sPi   = sPiT + 128 * PSTRIDE;
    float* sU    = sPi  + 128 * 128;
    float* sV    = sU   + TILE_R * USTRIDE;
    float* sNorm = sV   + TILE_R * USTRIDE;
    float* sCen  = sNorm + TILE_R;

    const int tid = threadIdx.x;

    // Stage Pi in both layouts (once per block; block is persistent).
    for (int idx = tid; idx < D * D; idx += NTHREADS) {
        int j = idx >> 7;        // Pi row
        int k = idx & (D - 1);   // Pi col
        float p = Pi[idx];
        sPi[idx] = p;                 // sPi[k*128+c] = Pi[k][c] (same linear layout)
        sPiT[k * PSTRIDE + j] = p;    // transposed
    }
    if (tid < 16) sCen[tid] = cen[tid];

    // Interior boundaries -> registers (compile-time indexed, no spills).
    float b[15];
    #pragma unroll
    for (int i = 0; i < 15; i++) b[i] = bnd[i + 1];

    const int cg = tid & 31;   // column group: cols cg*4 .. cg*4+3
    const int rg = tid >> 5;   // row group:    rows rg*8 .. rg*8+7

    __syncthreads();

    for (int tile = blockIdx.x; tile < ntiles; tile += gridDim.x) {
        const int row0 = tile * TILE_R;

        // ---- Phase 1: load x tile, per-row norm, write normalized u to smem ----
        {
            int lrow = tid >> 2;      // 0..63 local row
            int sub  = tid & 3;       // 4 threads per row, 32 floats each
            int grow = row0 + lrow;
            const float4* xp = (const float4*)(x + (size_t)grow * D) + sub * 8;
            float4 v[8];
            float ss = 0.f;
            #pragma unroll
            for (int i = 0; i < 8; i++) {
                float4 t = (grow < nrows) ? xp[i] : make_float4(0.f, 0.f, 0.f, 0.f);
                v[i] = t;
                ss += t.x * t.x + t.y * t.y + t.z * t.z + t.w * t.w;
            }
            // reduce across the 4 threads of this row (lane groups aligned to 4)
            ss += __shfl_xor_sync(0xffffffffu, ss, 1);
            ss += __shfl_xor_sync(0xffffffffu, ss, 2);
            float norm = sqrtf(ss);
            float inv  = 1.0f / (norm + 1e-8f);
            float4* up = (float4*)(sU + lrow * USTRIDE) + sub * 8;
            #pragma unroll
            for (int i = 0; i < 8; i++) {
                float4 t = v[i];
                t.x *= inv; t.y *= inv; t.z *= inv; t.w *= inv;
                up[i] = t;
            }
            if (sub == 0)  // fp16 round-trip of the norm, as in the reference
                sNorm[lrow] = __half2float(__float2half_rn(norm));
        }
        __syncthreads();

        // ---- GEMM1: rotated[r][c] = sum_k u[r][k] * Pi[c][k]  (8x4 per thread) ----
        float acc[8][4];
        #pragma unroll
        for (int r = 0; r < 8; r++) {
            acc[r][0] = 0.f; acc[r][1] = 0.f; acc[r][2] = 0.f; acc[r][3] = 0.f;
        }
        #pragma unroll 2
        for (int k = 0; k < D; k += 4) {
            float4 p0 = *(const float4*)&sPiT[(k + 0) * PSTRIDE + cg * 4];
            float4 p1 = *(const float4*)&sPiT[(k + 1) * PSTRIDE + cg * 4];
            float4 p2 = *(const float4*)&sPiT[(k + 2) * PSTRIDE + cg * 4];
            float4 p3 = *(const float4*)&sPiT[(k + 3) * PSTRIDE + cg * 4];
            #pragma unroll
            for (int r = 0; r < 8; r++) {
                float4 u4 = *(const float4*)&sU[(rg * 8 + r) * USTRIDE + k];
                acc[r][0] += u4.x * p0.x; acc[r][1] += u4.x * p0.y;
                acc[r][2] += u4.x * p0.z; acc[r][3] += u4.x * p0.w;
                acc[r][0] += u4.y * p1.x; acc[r][1] += u4.y * p1.y;
                acc[r][2] += u4.y * p1.z; acc[r][3] += u4.y * p1.w;
                acc[r][0] += u4.z * p2.x; acc[r][1] += u4.z * p2.y;
                acc[r][2] += u4.z * p2.z; acc[r][3] += u4.z * p2.w;
                acc[r][0] += u4.w * p3.x; acc[r][1] += u4.w * p3.y;
                acc[r][2] += u4.w * p3.z; acc[r][3] += u4.w * p3.w;
            }
        }

        // ---- Bucketize (searchsorted left == count(b < x)) + codebook gather ----
        #pragma unroll
        for (int r = 0; r < 8; r++) {
            float4 vv;
            #pragma unroll
            for (int c = 0; c < 4; c++) {
                float xv = acc[r][c];
                int idx = 0;
                #pragma unroll
                for (int i = 0; i < 15; i++) idx += (xv > b[i]) ? 1 : 0;
                ((float*)&vv)[c] = sCen[idx];
            }
            *(float4*)&sV[(rg * 8 + r) * USTRIDE + cg * 4] = vv;
        }
        __syncthreads();

        // ---- GEMM2: recon[r][c] = sum_k v[r][k] * Pi[k][c] ----
        float acc2[8][4];
        #pragma unroll
        for (int r = 0; r < 8; r++) {
            acc2[r][0] = 0.f; acc2[r][1] = 0.f; acc2[r][2] = 0.f; acc2[r][3] = 0.f;
        }
        #pragma unroll 2
        for (int k = 0; k < D; k += 4) {
            float4 p0 = *(const float4*)&sPi[(k + 0) * D + cg * 4];
            float4 p1 = *(const float4*)&sPi[(k + 1) * D + cg * 4];
            float4 p2 = *(const float4*)&sPi[(k + 2) * D + cg * 4];
            float4 p3 = *(const float4*)&sPi[(k + 3) * D + cg * 4];
            #pragma unroll
            for (int r = 0; r < 8; r++) {
                float4 v4 = *(const float4*)&sV[(rg * 8 + r) * USTRIDE + k];
                acc2[r][0] += v4.x * p0.x; acc2[r][1] += v4.x * p0.y;
                acc2[r][2] += v4.x * p0.z; acc2[r][3] += v4.x * p0.w;
                acc2[r][0] += v4.y * p1.x; acc2[r][1] += v4.y * p1.y;
                acc2[r][2] += v4.y * p1.z; acc2[r][3] += v4.y * p1.w;
                acc2[r][0] += v4.z * p2.x; acc2[r][1] += v4.z * p2.y;
                acc2[r][2] += v4.z * p2.z; acc2[r][3] += v4.z * p2.w;
                acc2[r][0] += v4.w * p3.x; acc2[r][1] += v4.w * p3.y;
                acc2[r][2] += v4.w * p3.z; acc2[r][3] += v4.w * p3.w;
            }
        }

        // ---- Epilogue: rescale by fp16-roundtripped norm, coalesced float4 store ----
        #pragma unroll
        for (int r = 0; r < 8; r++) {
            int grow = row0 + rg * 8 + r;
            if (grow < nrows) {
                float nq = sNorm[rg * 8 + r];
                float4 o;
                o.x = acc2[r][0] * nq; o.y = acc2[r][1] * nq;
                o.z = acc2[r][2] * nq; o.w = acc2[r][3] * nq;
                *(float4*)(out + (size_t)grow * D + cg * 4) = o;
            }
        }
        __syncthreads();  // protect sU/sNorm before next tile's phase 1
    }
}

extern "C" void kernel_launch(void* const* d_in, const int* in_sizes, int n_in,
                              void* d_out, int out_size)
{
    const float* x   = (const float*)d_in[0];
    const float* Pi  = (const float*)d_in[1];
    const float* cen = (const float*)d_in[2];
    const float* bnd = (const float*)d_in[3];
    float* out = (float*)d_out;

    int nrows  = in_sizes[0] / D;
    int ntiles = (nrows + TILE_R - 1) / TILE_R;

    size_t smem = (size_t)SMEM_FLOATS * sizeof(float);
    cudaFuncSetAttribute(tq_kernel, cudaFuncAttributeMaxDynamicSharedMemorySize,
                         (int)smem);

    int dev = 0;
    cudaGetDevice(&dev);
    int nsm = 148;
    cudaDeviceGetAttribute(&nsm, cudaDevAttrMultiProcessorCount, dev);
    int grid = ntiles < nsm ? ntiles : nsm;

    tq_kernel<<<grid, NTHREADS, smem>>>(x, Pi, cen, bnd, out, nrows, ntiles);
}